// round 1
// baseline (speedup 1.0000x reference)
#include <cuda_runtime.h>
#include <math.h>

// Problem constants
#define Bn   16384
#define En   256
#define Vn   128
#define Tn   16
#define G3   768          // 3*En
#define OUT_UTT  ((size_t)Bn * Tn * Vn)          // 33,554,432
#define OUT_NOFF (OUT_UTT)                        // N starts here
#define OUT_ROFF (OUT_UTT + Bn)                   // reconst starts here

// ---------------- device scratch (no allocation allowed) ----------------
__device__ float g_h   [Bn * En];     // decoder GRU state
__device__ float g_henc[Bn * En];     // encoder GRU state
__device__ float g_emb [Bn * En];     // embedding buffer
__device__ float g_gi  [Bn * G3];     // input gates
__device__ float g_gh  [Bn * G3];     // hidden gates
__device__ float g_logits[Bn * Vn];
__device__ int   g_tok [Bn];          // current decoder feedback token (-1 == zero vector)
__device__ int   g_toks[Tn * Bn];     // per-step emitted tokens (for encoder)
__device__ int   g_N   [Bn];
__device__ unsigned char g_alive[Bn];

// ---------------- init ----------------
__global__ void k_init(const float* __restrict__ x) {
    int i = blockIdx.x * blockDim.x + threadIdx.x;
    if (i < Bn * En) { g_h[i] = x[i]; g_henc[i] = 0.f; }
    if (i < Bn)      { g_tok[i] = -1; g_alive[i] = 1; g_N[i] = Tn; }
}

__global__ void k_zero_out(float* __restrict__ out, size_t n4, size_t n) {
    size_t i = (size_t)blockIdx.x * blockDim.x + threadIdx.x;
    if (i < n4) reinterpret_cast<float4*>(out)[i] = make_float4(0.f, 0.f, 0.f, 0.f);
    // tail
    size_t t = n4 * 4 + i;
    if (t < n) out[t] = 0.f;
}

// ---------------- embedding gather: emb[b] = Wd2e[:, tok[b]] + bd2e ----------------
__global__ void k_gather(const float* __restrict__ Wd2e, const float* __restrict__ bd2e,
                         const int* __restrict__ tok, float* __restrict__ emb) {
    int i = blockIdx.x * blockDim.x + threadIdx.x;
    if (i >= Bn * En) return;
    int b = i >> 8;          // /En
    int e = i & 255;         // %En
    int tk = tok[b];
    float v = bd2e[e];
    if (tk >= 0) v += Wd2e[e * Vn + tk];
    emb[i] = v;
}

// ---------------- tiled fp32 GEMM: C[b,j] = bias[j] + sum_e W[j,e]*A[b,e] ----------------
// A: [Bn x 256] row-major, W: [N x 256] row-major, C: [Bn x N]. K fixed = 256.
#define BM 64
#define BN 64
#define BK 16
__global__ __launch_bounds__(256) void k_gemm(const float* __restrict__ A,
                                              const float* __restrict__ W,
                                              const float* __restrict__ bias,
                                              float* __restrict__ C, int N) {
    __shared__ float As[BK][BM + 4];
    __shared__ float Ws[BK][BN + 4];
    int tid = threadIdx.x;
    int r0 = blockIdx.x * BM;
    int c0 = blockIdx.y * BN;
    int ty = tid >> 4;          // 0..15
    int tx = tid & 15;          // 0..15

    float acc[4][4];
#pragma unroll
    for (int i = 0; i < 4; i++)
#pragma unroll
        for (int j = 0; j < 4; j++) acc[i][j] = 0.f;

    int lr  = tid >> 2;         // 0..63 tile row
    int lk4 = (tid & 3) * 4;    // k offset within tile (float4 granule)
    const float* Ag = A + (size_t)(r0 + lr) * 256 + lk4;
    const float* Wg = W + (size_t)(c0 + lr) * 256 + lk4;

    for (int k0 = 0; k0 < 256; k0 += BK) {
        float4 av = *reinterpret_cast<const float4*>(Ag + k0);
        float4 wv = *reinterpret_cast<const float4*>(Wg + k0);
        __syncthreads();
        As[lk4 + 0][lr] = av.x; As[lk4 + 1][lr] = av.y;
        As[lk4 + 2][lr] = av.z; As[lk4 + 3][lr] = av.w;
        Ws[lk4 + 0][lr] = wv.x; Ws[lk4 + 1][lr] = wv.y;
        Ws[lk4 + 2][lr] = wv.z; Ws[lk4 + 3][lr] = wv.w;
        __syncthreads();
#pragma unroll
        for (int k = 0; k < BK; k++) {
            float4 a = *reinterpret_cast<const float4*>(&As[k][ty * 4]);
            float4 b = *reinterpret_cast<const float4*>(&Ws[k][tx * 4]);
            acc[0][0] += a.x * b.x; acc[0][1] += a.x * b.y; acc[0][2] += a.x * b.z; acc[0][3] += a.x * b.w;
            acc[1][0] += a.y * b.x; acc[1][1] += a.y * b.y; acc[1][2] += a.y * b.z; acc[1][3] += a.y * b.w;
            acc[2][0] += a.z * b.x; acc[2][1] += a.z * b.y; acc[2][2] += a.z * b.z; acc[2][3] += a.z * b.w;
            acc[3][0] += a.w * b.x; acc[3][1] += a.w * b.y; acc[3][2] += a.w * b.z; acc[3][3] += a.w * b.w;
        }
    }
    float bj[4];
#pragma unroll
    for (int j = 0; j < 4; j++) bj[j] = bias[c0 + tx * 4 + j];
#pragma unroll
    for (int i = 0; i < 4; i++) {
        float* Cr = C + (size_t)(r0 + ty * 4 + i) * N + c0 + tx * 4;
#pragma unroll
        for (int j = 0; j < 4; j++) Cr[j] = acc[i][j] + bj[j];
    }
}

// ---------------- fused GRU elementwise update ----------------
__device__ __forceinline__ float sigm(float x) { return 1.f / (1.f + expf(-x)); }

__global__ void k_gru(const float* __restrict__ gi, const float* __restrict__ gh,
                      float* __restrict__ h) {
    int i = blockIdx.x * blockDim.x + threadIdx.x;
    if (i >= Bn * En) return;
    int b = i >> 8;
    int j = i & 255;
    size_t base = (size_t)b * G3;
    float ir = gi[base + j],        hr = gh[base + j];
    float iz = gi[base + 256 + j],  hz = gh[base + 256 + j];
    float in_ = gi[base + 512 + j], hn = gh[base + 512 + j];
    float r = sigm(ir + hr);
    float z = sigm(iz + hz);
    float n = tanhf(in_ + r * hn);
    h[i] = (1.f - z) * n + z * h[i];
}

// ---------------- gumbel + argmax + state update + one-hot emit ----------------
__global__ void k_argmax(const float* __restrict__ logits, const float* __restrict__ unif,
                         float* __restrict__ out, int t) {
    int gw = (blockIdx.x * blockDim.x + threadIdx.x) >> 5;
    int lane = threadIdx.x & 31;
    if (gw >= Bn) return;
    int b = gw;
    const float* lrow = logits + (size_t)b * Vn;
    const float* urow = unif + ((size_t)t * Bn + b) * Vn;
    float best = -INFINITY;
    int bidx = Vn;
#pragma unroll
    for (int c = 0; c < 4; c++) {
        int v = lane + 32 * c;
        float u = urow[v];
        float g = -logf(-logf(u + 1e-10f) + 1e-10f);
        float m = lrow[v] + g;
        if (m > best || (m == best && v < bidx)) { best = m; bidx = v; }
    }
#pragma unroll
    for (int off = 16; off; off >>= 1) {
        float ob = __shfl_xor_sync(0xffffffffu, best, off);
        int   oi = __shfl_xor_sync(0xffffffffu, bidx, off);
        if (ob > best || (ob == best && oi < bidx)) { best = ob; bidx = oi; }
    }
    if (lane == 0) {
        bool ended = (bidx == 0);
        if (ended) g_N[b] = min(g_N[b], t);
        unsigned char an = (unsigned char)(g_alive[b] && !ended);
        g_alive[b] = an;
        int tk = an ? bidx : -1;
        g_tok[b] = tk;
        g_toks[t * Bn + b] = tk;
        if (an) out[(size_t)b * Tn * Vn + (size_t)t * Vn + bidx] = 1.0f;
    }
}

// ---------------- final: write N (as float) and reconst ----------------
__global__ void k_final(float* __restrict__ out) {
    int i = blockIdx.x * blockDim.x + threadIdx.x;
    if (i < Bn * En) out[OUT_ROFF + i] = g_henc[i];
    if (i < Bn)      out[OUT_NOFF + i] = (float)g_N[i];
}

// ---------------- host ----------------
extern "C" void kernel_launch(void* const* d_in, const int* in_sizes, int n_in,
                              void* d_out, int out_size) {
    const float* x        = (const float*)d_in[0];
    // d_in[1] = global_idxes (unused by forward)
    const float* unif     = (const float*)d_in[2];
    const float* dec_Wd2e = (const float*)d_in[3];
    const float* dec_bd2e = (const float*)d_in[4];
    const float* dec_Wih  = (const float*)d_in[5];
    const float* dec_Whh  = (const float*)d_in[6];
    const float* dec_bih  = (const float*)d_in[7];
    const float* dec_bhh  = (const float*)d_in[8];
    const float* dec_We2d = (const float*)d_in[9];
    const float* dec_be2d = (const float*)d_in[10];
    const float* enc_Wd2e = (const float*)d_in[11];
    const float* enc_bd2e = (const float*)d_in[12];
    const float* enc_Wih  = (const float*)d_in[13];
    const float* enc_Whh  = (const float*)d_in[14];
    const float* enc_bih  = (const float*)d_in[15];
    const float* enc_bhh  = (const float*)d_in[16];
    float* out = (float*)d_out;

    // resolve scratch symbol addresses (host API, not a stream op — capture-safe)
    void *p_h, *p_henc, *p_emb, *p_gi, *p_gh, *p_logits, *p_tok, *p_toks;
    cudaGetSymbolAddress(&p_h, g_h);
    cudaGetSymbolAddress(&p_henc, g_henc);
    cudaGetSymbolAddress(&p_emb, g_emb);
    cudaGetSymbolAddress(&p_gi, g_gi);
    cudaGetSymbolAddress(&p_gh, g_gh);
    cudaGetSymbolAddress(&p_logits, g_logits);
    cudaGetSymbolAddress(&p_tok, g_tok);
    cudaGetSymbolAddress(&p_toks, g_toks);
    float* hbuf   = (float*)p_h;
    float* hencb  = (float*)p_henc;
    float* emb    = (float*)p_emb;
    float* gi     = (float*)p_gi;
    float* gh     = (float*)p_gh;
    float* logits = (float*)p_logits;
    int*   tok    = (int*)p_tok;
    int*   toks   = (int*)p_toks;

    const int NT = 256;
    const int gBE = (Bn * En + NT - 1) / NT;        // covers B*E (and B)
    size_t osz = (size_t)out_size;
    size_t n4 = osz / 4;
    int gz = (int)((n4 + NT - 1) / NT);

    k_zero_out<<<gz, NT>>>(out, n4, osz);
    k_init<<<gBE, NT>>>(x);

    dim3 gemmBlk(256);
    dim3 gridGates(Bn / BM, G3 / BN);   // 256 x 12
    dim3 gridLogit(Bn / BM, Vn / BN);   // 256 x 2

    // ---------------- decoder: T sequential steps ----------------
    for (int t = 0; t < Tn; t++) {
        k_gather<<<gBE, NT>>>(dec_Wd2e, dec_bd2e, tok, emb);
        k_gemm<<<gridGates, gemmBlk>>>(emb,  dec_Wih, dec_bih, gi, G3);
        k_gemm<<<gridGates, gemmBlk>>>(hbuf, dec_Whh, dec_bhh, gh, G3);
        k_gru<<<gBE, NT>>>(gi, gh, hbuf);
        k_gemm<<<gridLogit, gemmBlk>>>(hbuf, dec_We2d, dec_be2d, logits, Vn);
        k_argmax<<<(Bn * 32 + NT - 1) / NT, NT>>>(logits, unif, out, t);
    }

    // ---------------- encoder: T sequential steps ----------------
    for (int t = 0; t < Tn; t++) {
        k_gather<<<gBE, NT>>>(enc_Wd2e, enc_bd2e, toks + t * Bn, emb);
        k_gemm<<<gridGates, gemmBlk>>>(emb,   enc_Wih, enc_bih, gi, G3);
        k_gemm<<<gridGates, gemmBlk>>>(hencb, enc_Whh, enc_bhh, gh, G3);
        k_gru<<<gBE, NT>>>(gi, gh, hencb);
    }

    k_final<<<gBE, NT>>>(out);
}

// round 2
// speedup vs baseline: 2.6093x; 2.6093x over previous
#include <cuda_runtime.h>
#include <math.h>

#define Bn 16384
#define En 256
#define Vn 128
#define Tn 16
#define G3 768

#define OUT_UTT  ((size_t)Bn * Tn * Vn)
#define OUT_NOFF (OUT_UTT)
#define OUT_ROFF (OUT_UTT + Bn)

// ---------------- device scratch ----------------
__device__ float g_h [2][Bn * En];    // decoder state ping-pong
__device__ float g_he[2][Bn * En];    // encoder state ping-pong
__device__ float g_Mdec[Vn * G3];     // [tok][gatecol] = (Wih @ Wd2e)^T
__device__ float g_cdec[G3];          // Wih@bd2e + bih
__device__ float g_Menc[Vn * G3];
__device__ float g_cenc[G3];
__device__ int   g_tok [Bn];          // decoder feedback token (-1 = zero vector)
__device__ int   g_toks[Tn * Bn];     // emitted tokens per step (encoder input)
__device__ int   g_N   [Bn];
__device__ unsigned char g_alive[Bn];

// ---------------- init ----------------
__global__ void k_init(const float* __restrict__ x) {
    int i = blockIdx.x * blockDim.x + threadIdx.x;
    if (i < Bn * En) { g_h[0][i] = x[i]; g_he[0][i] = 0.f; }
    if (i < Bn)      { g_tok[i] = -1; g_alive[i] = 1; g_N[i] = Tn; }
}

__global__ void k_zero_out(float* __restrict__ out, size_t n4, size_t n) {
    size_t i = (size_t)blockIdx.x * blockDim.x + threadIdx.x;
    if (i < n4) reinterpret_cast<float4*>(out)[i] = make_float4(0.f, 0.f, 0.f, 0.f);
    size_t t = n4 * 4 + i;
    if (t < n) out[t] = 0.f;
}

// ---------------- precompute M = (Wih @ Wd2e)^T  and cvec = Wih@bd2e + bih ----------------
// grid (Vn, 3), 256 threads; thread computes M[v][j], j = by*256 + tid
__global__ void k_prep(const float* __restrict__ Wih, const float* __restrict__ Wd2e,
                       const float* __restrict__ bd2e, const float* __restrict__ bih,
                       float* __restrict__ M, float* __restrict__ cvec) {
    int v = blockIdx.x;
    int j = blockIdx.y * 256 + threadIdx.x;
    const float* wr = Wih + (size_t)j * En;
    float acc = 0.f;
    for (int e = 0; e < En; e++) acc += wr[e] * Wd2e[e * Vn + v];
    M[v * G3 + j] = acc;
    if (v == 0) {
        float c = bih[j];
        for (int e = 0; e < En; e++) c += wr[e] * bd2e[e];
        cvec[j] = c;
    }
}

__device__ __forceinline__ float sigm(float x) { return 1.f / (1.f + expf(-x)); }

// ---------------- fused gates GEMM + GRU update ----------------
// grid (Bn/64, 4), 256 threads. Block: rows r0..r0+63, state cols j0..j0+63
// computes gh = h @ Whh^T (cols {g*256+j0..+63}, K=256), adds gi = M[tok] + cvec,
// applies GRU, writes hout[rows, j0..j0+63].
__global__ __launch_bounds__(256, 2) void k_gates(
    const float* __restrict__ hin, float* __restrict__ hout,
    const float* __restrict__ Whh, const float* __restrict__ bhh,
    const float* __restrict__ M, const float* __restrict__ cvec,
    const int* __restrict__ tok)
{
    __shared__ float As[2][16][68];
    __shared__ float Ws[2][16][196];
    const int t  = threadIdx.x;
    const int r0 = blockIdx.x * 64;
    const int j0 = blockIdx.y * 64;
    const int ty = t >> 4, tx = t & 15;

    // global load mapping
    const int lr  = t >> 2;          // 0..63
    const int lkq = (t & 3) * 4;     // 0,4,8,12
    const float* Ag  = hin + (size_t)(r0 + lr) * En + lkq;
    const float* Wg0 = Whh + (size_t)(0 * En + j0 + lr) * En + lkq;
    const float* Wg1 = Whh + (size_t)(1 * En + j0 + lr) * En + lkq;
    const float* Wg2 = Whh + (size_t)(2 * En + j0 + lr) * En + lkq;

    float4 av = *(const float4*)Ag;
    float4 w0 = *(const float4*)Wg0;
    float4 w1 = *(const float4*)Wg1;
    float4 w2 = *(const float4*)Wg2;

    float acc[3][4][4];
#pragma unroll
    for (int g = 0; g < 3; g++)
#pragma unroll
        for (int i = 0; i < 4; i++)
#pragma unroll
            for (int c = 0; c < 4; c++) acc[g][i][c] = 0.f;

    // store tile 0
    As[0][lkq+0][lr] = av.x; As[0][lkq+1][lr] = av.y; As[0][lkq+2][lr] = av.z; As[0][lkq+3][lr] = av.w;
    Ws[0][lkq+0][lr      ] = w0.x; Ws[0][lkq+1][lr      ] = w0.y; Ws[0][lkq+2][lr      ] = w0.z; Ws[0][lkq+3][lr      ] = w0.w;
    Ws[0][lkq+0][64  + lr] = w1.x; Ws[0][lkq+1][64  + lr] = w1.y; Ws[0][lkq+2][64  + lr] = w1.z; Ws[0][lkq+3][64  + lr] = w1.w;
    Ws[0][lkq+0][128 + lr] = w2.x; Ws[0][lkq+1][128 + lr] = w2.y; Ws[0][lkq+2][128 + lr] = w2.z; Ws[0][lkq+3][128 + lr] = w2.w;
    __syncthreads();

    for (int kt = 0; kt < 16; kt++) {
        const int buf = kt & 1;
        if (kt < 15) {
            av = *(const float4*)(Ag  + (kt + 1) * 16);
            w0 = *(const float4*)(Wg0 + (kt + 1) * 16);
            w1 = *(const float4*)(Wg1 + (kt + 1) * 16);
            w2 = *(const float4*)(Wg2 + (kt + 1) * 16);
        }
#pragma unroll
        for (int k = 0; k < 16; k++) {
            float a[4];
            float4 af = *(const float4*)&As[buf][k][ty * 4];
            a[0] = af.x; a[1] = af.y; a[2] = af.z; a[3] = af.w;
            float4 b0 = *(const float4*)&Ws[buf][k][      tx * 4];
            float4 b1 = *(const float4*)&Ws[buf][k][64  + tx * 4];
            float4 b2 = *(const float4*)&Ws[buf][k][128 + tx * 4];
            float b[3][4];
            b[0][0]=b0.x; b[0][1]=b0.y; b[0][2]=b0.z; b[0][3]=b0.w;
            b[1][0]=b1.x; b[1][1]=b1.y; b[1][2]=b1.z; b[1][3]=b1.w;
            b[2][0]=b2.x; b[2][1]=b2.y; b[2][2]=b2.z; b[2][3]=b2.w;
#pragma unroll
            for (int i = 0; i < 4; i++)
#pragma unroll
                for (int g = 0; g < 3; g++)
#pragma unroll
                    for (int c = 0; c < 4; c++)
                        acc[g][i][c] += a[i] * b[g][c];
        }
        if (kt < 15) {
            const int nb = buf ^ 1;
            As[nb][lkq+0][lr] = av.x; As[nb][lkq+1][lr] = av.y; As[nb][lkq+2][lr] = av.z; As[nb][lkq+3][lr] = av.w;
            Ws[nb][lkq+0][lr      ] = w0.x; Ws[nb][lkq+1][lr      ] = w0.y; Ws[nb][lkq+2][lr      ] = w0.z; Ws[nb][lkq+3][lr      ] = w0.w;
            Ws[nb][lkq+0][64  + lr] = w1.x; Ws[nb][lkq+1][64  + lr] = w1.y; Ws[nb][lkq+2][64  + lr] = w1.z; Ws[nb][lkq+3][64  + lr] = w1.w;
            Ws[nb][lkq+0][128 + lr] = w2.x; Ws[nb][lkq+1][128 + lr] = w2.y; Ws[nb][lkq+2][128 + lr] = w2.z; Ws[nb][lkq+3][128 + lr] = w2.w;
            __syncthreads();
        }
    }

    // epilogue: gi gather + bias + GRU
    float cv[3][4], bh[3][4];
#pragma unroll
    for (int g = 0; g < 3; g++) {
        float4 cf = *(const float4*)(cvec + g * En + j0 + tx * 4);
        cv[g][0]=cf.x; cv[g][1]=cf.y; cv[g][2]=cf.z; cv[g][3]=cf.w;
        float4 bf = *(const float4*)(bhh + g * En + j0 + tx * 4);
        bh[g][0]=bf.x; bh[g][1]=bf.y; bh[g][2]=bf.z; bh[g][3]=bf.w;
    }
#pragma unroll
    for (int i = 0; i < 4; i++) {
        const int rr = r0 + ty * 4 + i;
        const int tk = tok[rr];
        float m[3][4];
        if (tk >= 0) {
            const float* Mr = M + (size_t)tk * G3 + j0 + tx * 4;
#pragma unroll
            for (int g = 0; g < 3; g++) {
                float4 mf = *(const float4*)(Mr + g * En);
                m[g][0]=mf.x; m[g][1]=mf.y; m[g][2]=mf.z; m[g][3]=mf.w;
            }
        } else {
#pragma unroll
            for (int g = 0; g < 3; g++)
#pragma unroll
                for (int c = 0; c < 4; c++) m[g][c] = 0.f;
        }
        float4 hof = *(const float4*)(hin + (size_t)rr * En + j0 + tx * 4);
        float hold[4] = {hof.x, hof.y, hof.z, hof.w};
        float hnew[4];
#pragma unroll
        for (int c = 0; c < 4; c++) {
            float ir = m[0][c] + cv[0][c], hr = acc[0][i][c] + bh[0][c];
            float iz = m[1][c] + cv[1][c], hz = acc[1][i][c] + bh[1][c];
            float in_= m[2][c] + cv[2][c], hn = acc[2][i][c] + bh[2][c];
            float r = sigm(ir + hr);
            float z = sigm(iz + hz);
            float n = tanhf(in_ + r * hn);
            hnew[c] = (1.f - z) * n + z * hold[c];
        }
        float4 ho = make_float4(hnew[0], hnew[1], hnew[2], hnew[3]);
        *(float4*)(hout + (size_t)rr * En + j0 + tx * 4) = ho;
    }
}

// ---------------- fused logits GEMM + gumbel + argmax + token update ----------------
// grid Bn/64, 256 threads. Block: rows r0..r0+63, all 128 logit cols, K=256.
__global__ __launch_bounds__(256, 2) void k_logits(
    const float* __restrict__ hin, const float* __restrict__ We2d,
    const float* __restrict__ be2d, const float* __restrict__ unif,
    float* __restrict__ out, int t)
{
    __shared__ float As[2][16][68];
    __shared__ float Ws[2][16][132];
    __shared__ float sVal[64][17];
    __shared__ int   sIdx[64][17];
    const int tid = threadIdx.x;
    const int r0 = blockIdx.x * 64;
    const int ty = tid >> 4, tx = tid & 15;

    const int lr  = tid >> 2;
    const int lkq = (tid & 3) * 4;
    const float* Ag = hin + (size_t)(r0 + lr) * En + lkq;
    const int wn  = tid >> 1;          // 0..127
    const int wkq = (tid & 1) * 8;     // 0 or 8
    const float* Wg = We2d + (size_t)wn * En + wkq;

    float4 av = *(const float4*)Ag;
    float4 w0 = *(const float4*)Wg;
    float4 w1 = *(const float4*)(Wg + 4);

    float acc[4][8];
#pragma unroll
    for (int i = 0; i < 4; i++)
#pragma unroll
        for (int c = 0; c < 8; c++) acc[i][c] = 0.f;

    As[0][lkq+0][lr] = av.x; As[0][lkq+1][lr] = av.y; As[0][lkq+2][lr] = av.z; As[0][lkq+3][lr] = av.w;
    Ws[0][wkq+0][wn] = w0.x; Ws[0][wkq+1][wn] = w0.y; Ws[0][wkq+2][wn] = w0.z; Ws[0][wkq+3][wn] = w0.w;
    Ws[0][wkq+4][wn] = w1.x; Ws[0][wkq+5][wn] = w1.y; Ws[0][wkq+6][wn] = w1.z; Ws[0][wkq+7][wn] = w1.w;
    __syncthreads();

    for (int kt = 0; kt < 16; kt++) {
        const int buf = kt & 1;
        if (kt < 15) {
            av = *(const float4*)(Ag + (kt + 1) * 16);
            w0 = *(const float4*)(Wg + (kt + 1) * 16);
            w1 = *(const float4*)(Wg + (kt + 1) * 16 + 4);
        }
#pragma unroll
        for (int k = 0; k < 16; k++) {
            float4 af = *(const float4*)&As[buf][k][ty * 4];
            float a[4] = {af.x, af.y, af.z, af.w};
            float4 b0 = *(const float4*)&Ws[buf][k][     tx * 4];
            float4 b1 = *(const float4*)&Ws[buf][k][64 + tx * 4];
            float b[8] = {b0.x, b0.y, b0.z, b0.w, b1.x, b1.y, b1.z, b1.w};
#pragma unroll
            for (int i = 0; i < 4; i++)
#pragma unroll
                for (int c = 0; c < 8; c++) acc[i][c] += a[i] * b[c];
        }
        if (kt < 15) {
            const int nb = buf ^ 1;
            As[nb][lkq+0][lr] = av.x; As[nb][lkq+1][lr] = av.y; As[nb][lkq+2][lr] = av.z; As[nb][lkq+3][lr] = av.w;
            Ws[nb][wkq+0][wn] = w0.x; Ws[nb][wkq+1][wn] = w0.y; Ws[nb][wkq+2][wn] = w0.z; Ws[nb][wkq+3][wn] = w0.w;
            Ws[nb][wkq+4][wn] = w1.x; Ws[nb][wkq+5][wn] = w1.y; Ws[nb][wkq+6][wn] = w1.z; Ws[nb][wkq+7][wn] = w1.w;
            __syncthreads();
        }
    }

    // epilogue: bias + gumbel noise, local argmax over 8 cols
    float be[8];
    {
        float4 b0 = *(const float4*)(be2d +      tx * 4);
        float4 b1 = *(const float4*)(be2d + 64 + tx * 4);
        be[0]=b0.x; be[1]=b0.y; be[2]=b0.z; be[3]=b0.w;
        be[4]=b1.x; be[5]=b1.y; be[6]=b1.z; be[7]=b1.w;
    }
#pragma unroll
    for (int i = 0; i < 4; i++) {
        const int rr = r0 + ty * 4 + i;
        const float* urow = unif + ((size_t)t * Bn + rr) * Vn;
        float best = -INFINITY; int bidx = Vn;
#pragma unroll
        for (int c = 0; c < 8; c++) {
            const int col = (c < 4) ? (tx * 4 + c) : (64 + tx * 4 + (c - 4));
            float u = urow[col];
            float g = -logf(-logf(u + 1e-10f) + 1e-10f);
            float v = acc[i][c] + be[c] + g;
            if (v > best || (v == best && col < bidx)) { best = v; bidx = col; }
        }
        sVal[ty * 4 + i][tx] = best;
        sIdx[ty * 4 + i][tx] = bidx;
    }
    __syncthreads();

    if (tid < 64) {
        const int b = r0 + tid;
        float best = sVal[tid][0]; int bidx = sIdx[tid][0];
#pragma unroll
        for (int j = 1; j < 16; j++) {
            float v = sVal[tid][j]; int ix = sIdx[tid][j];
            if (v > best || (v == best && ix < bidx)) { best = v; bidx = ix; }
        }
        bool ended = (bidx == 0);
        if (ended) g_N[b] = min(g_N[b], t);
        unsigned char an = (unsigned char)(g_alive[b] && !ended);
        g_alive[b] = an;
        int tk = an ? bidx : -1;
        g_tok[b] = tk;
        g_toks[t * Bn + b] = tk;
        if (an) out[(size_t)b * Tn * Vn + (size_t)t * Vn + bidx] = 1.0f;
    }
}

// ---------------- final: write N and reconst ----------------
__global__ void k_final(float* __restrict__ out) {
    int i = blockIdx.x * blockDim.x + threadIdx.x;
    if (i < Bn * En) out[OUT_ROFF + i] = g_he[0][i];
    if (i < Bn)      out[OUT_NOFF + i] = (float)g_N[i];
}

// ---------------- host ----------------
extern "C" void kernel_launch(void* const* d_in, const int* in_sizes, int n_in,
                              void* d_out, int out_size) {
    const float* x        = (const float*)d_in[0];
    const float* unif     = (const float*)d_in[2];
    const float* dec_Wd2e = (const float*)d_in[3];
    const float* dec_bd2e = (const float*)d_in[4];
    const float* dec_Wih  = (const float*)d_in[5];
    const float* dec_Whh  = (const float*)d_in[6];
    const float* dec_bih  = (const float*)d_in[7];
    const float* dec_bhh  = (const float*)d_in[8];
    const float* dec_We2d = (const float*)d_in[9];
    const float* dec_be2d = (const float*)d_in[10];
    const float* enc_Wd2e = (const float*)d_in[11];
    const float* enc_bd2e = (const float*)d_in[12];
    const float* enc_Wih  = (const float*)d_in[13];
    const float* enc_Whh  = (const float*)d_in[14];
    const float* enc_bih  = (const float*)d_in[15];
    const float* enc_bhh  = (const float*)d_in[16];
    float* out = (float*)d_out;

    void *p_h, *p_he, *p_Mdec, *p_cdec, *p_Menc, *p_cenc, *p_tok, *p_toks;
    cudaGetSymbolAddress(&p_h,    g_h);
    cudaGetSymbolAddress(&p_he,   g_he);
    cudaGetSymbolAddress(&p_Mdec, g_Mdec);
    cudaGetSymbolAddress(&p_cdec, g_cdec);
    cudaGetSymbolAddress(&p_Menc, g_Menc);
    cudaGetSymbolAddress(&p_cenc, g_cenc);
    cudaGetSymbolAddress(&p_tok,  g_tok);
    cudaGetSymbolAddress(&p_toks, g_toks);
    float* hb[2]  = { (float*)p_h,  (float*)p_h  + (size_t)Bn * En };
    float* heb[2] = { (float*)p_he, (float*)p_he + (size_t)Bn * En };
    float* Mdec = (float*)p_Mdec; float* cdec = (float*)p_cdec;
    float* Menc = (float*)p_Menc; float* cenc = (float*)p_cenc;
    int* tok = (int*)p_tok; int* toks = (int*)p_toks;

    const int NT = 256;
    const int gBE = (Bn * En + NT - 1) / NT;
    size_t osz = (size_t)out_size;
    size_t n4 = osz / 4;
    int gz = (int)((n4 + NT - 1) / NT);

    k_zero_out<<<gz, NT>>>(out, n4, osz);
    k_init<<<gBE, NT>>>(x);
    k_prep<<<dim3(Vn, 3), NT>>>(dec_Wih, dec_Wd2e, dec_bd2e, dec_bih, Mdec, cdec);
    k_prep<<<dim3(Vn, 3), NT>>>(enc_Wih, enc_Wd2e, enc_bd2e, enc_bih, Menc, cenc);

    dim3 gGates(Bn / 64, 4);
    dim3 gLog(Bn / 64);

    // decoder
    for (int t = 0; t < Tn; t++) {
        k_gates<<<gGates, NT>>>(hb[t & 1], hb[(t + 1) & 1], dec_Whh, dec_bhh, Mdec, cdec, tok);
        k_logits<<<gLog, NT>>>(hb[(t + 1) & 1], dec_We2d, dec_be2d, unif, out, t);
    }
    // encoder
    for (int t = 0; t < Tn; t++) {
        k_gates<<<gGates, NT>>>(heb[t & 1], heb[(t + 1) & 1], enc_Whh, enc_bhh, Menc, cenc, toks + t * Bn);
    }
    k_final<<<gBE, NT>>>(out);
}

// round 3
// speedup vs baseline: 2.7704x; 1.0617x over previous
#include <cuda_runtime.h>
#include <math.h>

#define Bn 16384
#define En 256
#define Vn 128
#define Tn 16
#define G3 768

#define OUT_UTT  ((size_t)Bn * Tn * Vn)
#define OUT_NOFF (OUT_UTT)
#define OUT_ROFF (OUT_UTT + Bn)

typedef unsigned long long ull;

// ---------------- packed f32x2 helpers ----------------
__device__ __forceinline__ ull pack2(float x, float y) {
    ull r;
    asm("mov.b64 %0, {%1, %2};" : "=l"(r) : "f"(x), "f"(y));
    return r;
}
__device__ __forceinline__ void unpack2(ull v, float& x, float& y) {
    asm("mov.b64 {%0, %1}, %2;" : "=f"(x), "=f"(y) : "l"(v));
}
__device__ __forceinline__ void fma2(ull& c, ull a, ull b) {
    asm("fma.rn.f32x2 %0, %1, %2, %3;" : "=l"(c) : "l"(a), "l"(b), "l"(c));
}

// ---------------- device scratch ----------------
__device__ float g_h [2][Bn * En];
__device__ float g_he[2][Bn * En];
__device__ float g_Mdec[Vn * G3];
__device__ float g_cdec[G3];
__device__ float g_Menc[Vn * G3];
__device__ float g_cenc[G3];
__device__ int   g_tok [Bn];
__device__ int   g_toks[Tn * Bn];
__device__ int   g_N   [Bn];
__device__ unsigned char g_alive[Bn];

// ---------------- init ----------------
__global__ void k_init(const float* __restrict__ x) {
    int i = blockIdx.x * blockDim.x + threadIdx.x;
    if (i < Bn * En) { g_h[0][i] = x[i]; g_he[0][i] = 0.f; }
    if (i < Bn)      { g_tok[i] = -1; g_alive[i] = 1; g_N[i] = Tn; }
}

__global__ void k_zero_out(float* __restrict__ out) {
    size_t i = (size_t)blockIdx.x * blockDim.x + threadIdx.x;
    if (i < OUT_UTT / 4) reinterpret_cast<float4*>(out)[i] = make_float4(0.f, 0.f, 0.f, 0.f);
}

// ---------------- precompute M = (Wih @ Wd2e)^T and cvec = Wih@bd2e + bih ----------------
// grid (Vn, G3/64). Block: 256 thr = 8 warps, warp handles 8 j's.
__global__ void k_prep(const float* __restrict__ Wih, const float* __restrict__ Wd2e,
                       const float* __restrict__ bd2e, const float* __restrict__ bih,
                       float* __restrict__ M, float* __restrict__ cvec) {
    __shared__ float sw[En];
    __shared__ float sb[En];
    const int v  = blockIdx.x;
    const int j0 = blockIdx.y * 64;
    for (int e = threadIdx.x; e < En; e += 256) {
        sw[e] = Wd2e[e * Vn + v];
        if (v == 0) sb[e] = bd2e[e];
    }
    __syncthreads();
    const int warp = threadIdx.x >> 5, lane = threadIdx.x & 31;
#pragma unroll
    for (int jj = 0; jj < 8; jj++) {
        const int j = j0 + warp * 8 + jj;
        const float* wr = Wih + (size_t)j * En;
        float s = 0.f, c = 0.f;
#pragma unroll
        for (int e = lane; e < En; e += 32) {
            float w = wr[e];
            s += w * sw[e];
            if (v == 0) c += w * sb[e];
        }
#pragma unroll
        for (int o = 16; o; o >>= 1) {
            s += __shfl_xor_sync(0xffffffffu, s, o);
            if (v == 0) c += __shfl_xor_sync(0xffffffffu, c, o);
        }
        if (lane == 0) {
            M[v * G3 + j] = s;
            if (v == 0) cvec[j] = bih[j] + c;
        }
    }
}

__device__ __forceinline__ float sigm(float x) { return 1.f / (1.f + expf(-x)); }

// ---------------- fused gates GEMM (f32x2) + GRU update ----------------
// grid (Bn/64, 4), 256 threads. rows r0..+63, state cols j0..+63, K=256.
__global__ __launch_bounds__(256, 2) void k_gates(
    const float* __restrict__ hin, float* __restrict__ hout,
    const float* __restrict__ Whh, const float* __restrict__ bhh,
    const float* __restrict__ M, const float* __restrict__ cvec,
    const int* __restrict__ tok)
{
    __shared__ float As[2][16][68];
    __shared__ float Ws[2][16][196];
    const int t  = threadIdx.x;
    const int r0 = blockIdx.x * 64;
    const int j0 = blockIdx.y * 64;
    const int ty = t >> 4, tx = t & 15;

    const int lr  = t >> 2;
    const int lkq = (t & 3) * 4;
    const float* Ag  = hin + (size_t)(r0 + lr) * En + lkq;
    const float* Wg0 = Whh + (size_t)(0 * En + j0 + lr) * En + lkq;
    const float* Wg1 = Whh + (size_t)(1 * En + j0 + lr) * En + lkq;
    const float* Wg2 = Whh + (size_t)(2 * En + j0 + lr) * En + lkq;

    float4 av = *(const float4*)Ag;
    float4 w0 = *(const float4*)Wg0;
    float4 w1 = *(const float4*)Wg1;
    float4 w2 = *(const float4*)Wg2;

    ull acc2[3][4][2];
#pragma unroll
    for (int g = 0; g < 3; g++)
#pragma unroll
        for (int i = 0; i < 4; i++) { acc2[g][i][0] = 0ull; acc2[g][i][1] = 0ull; }

    As[0][lkq+0][lr] = av.x; As[0][lkq+1][lr] = av.y; As[0][lkq+2][lr] = av.z; As[0][lkq+3][lr] = av.w;
    Ws[0][lkq+0][lr      ] = w0.x; Ws[0][lkq+1][lr      ] = w0.y; Ws[0][lkq+2][lr      ] = w0.z; Ws[0][lkq+3][lr      ] = w0.w;
    Ws[0][lkq+0][64  + lr] = w1.x; Ws[0][lkq+1][64  + lr] = w1.y; Ws[0][lkq+2][64  + lr] = w1.z; Ws[0][lkq+3][64  + lr] = w1.w;
    Ws[0][lkq+0][128 + lr] = w2.x; Ws[0][lkq+1][128 + lr] = w2.y; Ws[0][lkq+2][128 + lr] = w2.z; Ws[0][lkq+3][128 + lr] = w2.w;
    __syncthreads();

    for (int kt = 0; kt < 16; kt++) {
        const int buf = kt & 1;
        if (kt < 15) {
            av = *(const float4*)(Ag  + (kt + 1) * 16);
            w0 = *(const float4*)(Wg0 + (kt + 1) * 16);
            w1 = *(const float4*)(Wg1 + (kt + 1) * 16);
            w2 = *(const float4*)(Wg2 + (kt + 1) * 16);
        }
#pragma unroll
        for (int k = 0; k < 16; k++) {
            float4 af = *(const float4*)&As[buf][k][ty * 4];
            ull ap[4];
            ap[0] = pack2(af.x, af.x); ap[1] = pack2(af.y, af.y);
            ap[2] = pack2(af.z, af.z); ap[3] = pack2(af.w, af.w);
            ull bp[3][2];
#pragma unroll
            for (int g = 0; g < 3; g++) {
                bp[g][0] = *(const ull*)&Ws[buf][k][g * 64 + tx * 4];
                bp[g][1] = *(const ull*)&Ws[buf][k][g * 64 + tx * 4 + 2];
            }
#pragma unroll
            for (int i = 0; i < 4; i++)
#pragma unroll
                for (int g = 0; g < 3; g++) {
                    fma2(acc2[g][i][0], ap[i], bp[g][0]);
                    fma2(acc2[g][i][1], ap[i], bp[g][1]);
                }
        }
        if (kt < 15) {
            const int nb = buf ^ 1;
            As[nb][lkq+0][lr] = av.x; As[nb][lkq+1][lr] = av.y; As[nb][lkq+2][lr] = av.z; As[nb][lkq+3][lr] = av.w;
            Ws[nb][lkq+0][lr      ] = w0.x; Ws[nb][lkq+1][lr      ] = w0.y; Ws[nb][lkq+2][lr      ] = w0.z; Ws[nb][lkq+3][lr      ] = w0.w;
            Ws[nb][lkq+0][64  + lr] = w1.x; Ws[nb][lkq+1][64  + lr] = w1.y; Ws[nb][lkq+2][64  + lr] = w1.z; Ws[nb][lkq+3][64  + lr] = w1.w;
            Ws[nb][lkq+0][128 + lr] = w2.x; Ws[nb][lkq+1][128 + lr] = w2.y; Ws[nb][lkq+2][128 + lr] = w2.z; Ws[nb][lkq+3][128 + lr] = w2.w;
            __syncthreads();
        }
    }

    // epilogue
    float cv[3][4], bh[3][4];
#pragma unroll
    for (int g = 0; g < 3; g++) {
        float4 cf = *(const float4*)(cvec + g * En + j0 + tx * 4);
        cv[g][0]=cf.x; cv[g][1]=cf.y; cv[g][2]=cf.z; cv[g][3]=cf.w;
        float4 bf = *(const float4*)(bhh + g * En + j0 + tx * 4);
        bh[g][0]=bf.x; bh[g][1]=bf.y; bh[g][2]=bf.z; bh[g][3]=bf.w;
    }
#pragma unroll
    for (int i = 0; i < 4; i++) {
        const int rr = r0 + ty * 4 + i;
        const int tk = tok[rr];
        float m[3][4];
        if (tk >= 0) {
            const float* Mr = M + (size_t)tk * G3 + j0 + tx * 4;
#pragma unroll
            for (int g = 0; g < 3; g++) {
                float4 mf = *(const float4*)(Mr + g * En);
                m[g][0]=mf.x; m[g][1]=mf.y; m[g][2]=mf.z; m[g][3]=mf.w;
            }
        } else {
#pragma unroll
            for (int g = 0; g < 3; g++)
#pragma unroll
                for (int c = 0; c < 4; c++) m[g][c] = 0.f;
        }
        float acc[3][4];
#pragma unroll
        for (int g = 0; g < 3; g++) {
            unpack2(acc2[g][i][0], acc[g][0], acc[g][1]);
            unpack2(acc2[g][i][1], acc[g][2], acc[g][3]);
        }
        float4 hof = *(const float4*)(hin + (size_t)rr * En + j0 + tx * 4);
        float hold[4] = {hof.x, hof.y, hof.z, hof.w};
        float hnew[4];
#pragma unroll
        for (int c = 0; c < 4; c++) {
            float ir = m[0][c] + cv[0][c], hr = acc[0][c] + bh[0][c];
            float iz = m[1][c] + cv[1][c], hz = acc[1][c] + bh[1][c];
            float in_= m[2][c] + cv[2][c], hn = acc[2][c] + bh[2][c];
            float r = sigm(ir + hr);
            float z = sigm(iz + hz);
            float n = tanhf(in_ + r * hn);
            hnew[c] = (1.f - z) * n + z * hold[c];
        }
        *(float4*)(hout + (size_t)rr * En + j0 + tx * 4) = make_float4(hnew[0], hnew[1], hnew[2], hnew[3]);
    }
}

// ---------------- fused logits GEMM (f32x2) + gumbel + argmax + token update ----------------
__global__ __launch_bounds__(256, 2) void k_logits(
    const float* __restrict__ hin, const float* __restrict__ We2d,
    const float* __restrict__ be2d, const float* __restrict__ unif,
    float* __restrict__ out, int t)
{
    __shared__ float As[2][16][68];
    __shared__ float Ws[2][16][132];
    __shared__ float sVal[64][17];
    __shared__ int   sIdx[64][17];
    const int tid = threadIdx.x;
    const int r0 = blockIdx.x * 64;
    const int ty = tid >> 4, tx = tid & 15;

    const int lr  = tid >> 2;
    const int lkq = (tid & 3) * 4;
    const float* Ag = hin + (size_t)(r0 + lr) * En + lkq;
    const int wn  = tid >> 1;
    const int wkq = (tid & 1) * 8;
    const float* Wg = We2d + (size_t)wn * En + wkq;

    float4 av = *(const float4*)Ag;
    float4 w0 = *(const float4*)Wg;
    float4 w1 = *(const float4*)(Wg + 4);

    ull acc2[4][4];
#pragma unroll
    for (int i = 0; i < 4; i++)
#pragma unroll
        for (int p = 0; p < 4; p++) acc2[i][p] = 0ull;

    As[0][lkq+0][lr] = av.x; As[0][lkq+1][lr] = av.y; As[0][lkq+2][lr] = av.z; As[0][lkq+3][lr] = av.w;
    Ws[0][wkq+0][wn] = w0.x; Ws[0][wkq+1][wn] = w0.y; Ws[0][wkq+2][wn] = w0.z; Ws[0][wkq+3][wn] = w0.w;
    Ws[0][wkq+4][wn] = w1.x; Ws[0][wkq+5][wn] = w1.y; Ws[0][wkq+6][wn] = w1.z; Ws[0][wkq+7][wn] = w1.w;
    __syncthreads();

    for (int kt = 0; kt < 16; kt++) {
        const int buf = kt & 1;
        if (kt < 15) {
            av = *(const float4*)(Ag + (kt + 1) * 16);
            w0 = *(const float4*)(Wg + (kt + 1) * 16);
            w1 = *(const float4*)(Wg + (kt + 1) * 16 + 4);
        }
#pragma unroll
        for (int k = 0; k < 16; k++) {
            float4 af = *(const float4*)&As[buf][k][ty * 4];
            ull ap[4];
            ap[0] = pack2(af.x, af.x); ap[1] = pack2(af.y, af.y);
            ap[2] = pack2(af.z, af.z); ap[3] = pack2(af.w, af.w);
            ull bp[4];
            bp[0] = *(const ull*)&Ws[buf][k][     tx * 4];
            bp[1] = *(const ull*)&Ws[buf][k][     tx * 4 + 2];
            bp[2] = *(const ull*)&Ws[buf][k][64 + tx * 4];
            bp[3] = *(const ull*)&Ws[buf][k][64 + tx * 4 + 2];
#pragma unroll
            for (int i = 0; i < 4; i++)
#pragma unroll
                for (int p = 0; p < 4; p++) fma2(acc2[i][p], ap[i], bp[p]);
        }
        if (kt < 15) {
            const int nb = buf ^ 1;
            As[nb][lkq+0][lr] = av.x; As[nb][lkq+1][lr] = av.y; As[nb][lkq+2][lr] = av.z; As[nb][lkq+3][lr] = av.w;
            Ws[nb][wkq+0][wn] = w0.x; Ws[nb][wkq+1][wn] = w0.y; Ws[nb][wkq+2][wn] = w0.z; Ws[nb][wkq+3][wn] = w0.w;
            Ws[nb][wkq+4][wn] = w1.x; Ws[nb][wkq+5][wn] = w1.y; Ws[nb][wkq+6][wn] = w1.z; Ws[nb][wkq+7][wn] = w1.w;
            __syncthreads();
        }
    }

    float be[8];
    {
        float4 b0 = *(const float4*)(be2d +      tx * 4);
        float4 b1 = *(const float4*)(be2d + 64 + tx * 4);
        be[0]=b0.x; be[1]=b0.y; be[2]=b0.z; be[3]=b0.w;
        be[4]=b1.x; be[5]=b1.y; be[6]=b1.z; be[7]=b1.w;
    }
#pragma unroll
    for (int i = 0; i < 4; i++) {
        const int rr = r0 + ty * 4 + i;
        const float* urow = unif + ((size_t)t * Bn + rr) * Vn;
        float acc[8];
        unpack2(acc2[i][0], acc[0], acc[1]);
        unpack2(acc2[i][1], acc[2], acc[3]);
        unpack2(acc2[i][2], acc[4], acc[5]);
        unpack2(acc2[i][3], acc[6], acc[7]);
        float best = -INFINITY; int bidx = Vn;
#pragma unroll
        for (int c = 0; c < 8; c++) {
            const int col = (c < 4) ? (tx * 4 + c) : (64 + tx * 4 + (c - 4));
            float u = urow[col];
            float g = -logf(-logf(u + 1e-10f) + 1e-10f);
            float v = acc[c] + be[c] + g;
            if (v > best || (v == best && col < bidx)) { best = v; bidx = col; }
        }
        sVal[ty * 4 + i][tx] = best;
        sIdx[ty * 4 + i][tx] = bidx;
    }
    __syncthreads();

    if (tid < 64) {
        const int b = r0 + tid;
        float best = sVal[tid][0]; int bidx = sIdx[tid][0];
#pragma unroll
        for (int j = 1; j < 16; j++) {
            float v = sVal[tid][j]; int ix = sIdx[tid][j];
            if (v > best || (v == best && ix < bidx)) { best = v; bidx = ix; }
        }
        bool ended = (bidx == 0);
        if (ended) g_N[b] = min(g_N[b], t);
        unsigned char an = (unsigned char)(g_alive[b] && !ended);
        g_alive[b] = an;
        int tk = an ? bidx : -1;
        g_tok[b] = tk;
        g_toks[t * Bn + b] = tk;
        if (an) out[(size_t)b * Tn * Vn + (size_t)t * Vn + bidx] = 1.0f;
    }
}

// ---------------- final ----------------
__global__ void k_final(float* __restrict__ out) {
    int i = blockIdx.x * blockDim.x + threadIdx.x;
    if (i < Bn * En) out[OUT_ROFF + i] = g_he[0][i];
    if (i < Bn)      out[OUT_NOFF + i] = (float)g_N[i];
}

// ---------------- host ----------------
extern "C" void kernel_launch(void* const* d_in, const int* in_sizes, int n_in,
                              void* d_out, int out_size) {
    const float* x        = (const float*)d_in[0];
    const float* unif     = (const float*)d_in[2];
    const float* dec_Wd2e = (const float*)d_in[3];
    const float* dec_bd2e = (const float*)d_in[4];
    const float* dec_Wih  = (const float*)d_in[5];
    const float* dec_Whh  = (const float*)d_in[6];
    const float* dec_bih  = (const float*)d_in[7];
    const float* dec_bhh  = (const float*)d_in[8];
    const float* dec_We2d = (const float*)d_in[9];
    const float* dec_be2d = (const float*)d_in[10];
    const float* enc_Wd2e = (const float*)d_in[11];
    const float* enc_bd2e = (const float*)d_in[12];
    const float* enc_Wih  = (const float*)d_in[13];
    const float* enc_Whh  = (const float*)d_in[14];
    const float* enc_bih  = (const float*)d_in[15];
    const float* enc_bhh  = (const float*)d_in[16];
    float* out = (float*)d_out;

    void *p_h, *p_he, *p_Mdec, *p_cdec, *p_Menc, *p_cenc, *p_tok, *p_toks;
    cudaGetSymbolAddress(&p_h,    g_h);
    cudaGetSymbolAddress(&p_he,   g_he);
    cudaGetSymbolAddress(&p_Mdec, g_Mdec);
    cudaGetSymbolAddress(&p_cdec, g_cdec);
    cudaGetSymbolAddress(&p_Menc, g_Menc);
    cudaGetSymbolAddress(&p_cenc, g_cenc);
    cudaGetSymbolAddress(&p_tok,  g_tok);
    cudaGetSymbolAddress(&p_toks, g_toks);
    float* hb[2]  = { (float*)p_h,  (float*)p_h  + (size_t)Bn * En };
    float* heb[2] = { (float*)p_he, (float*)p_he + (size_t)Bn * En };
    float* Mdec = (float*)p_Mdec; float* cdec = (float*)p_cdec;
    float* Menc = (float*)p_Menc; float* cenc = (float*)p_cenc;
    int* tok = (int*)p_tok; int* toks = (int*)p_toks;

    const int NT = 256;
    const int gBE = (Bn * En + NT - 1) / NT;
    int gz = (int)((OUT_UTT / 4 + NT - 1) / NT);

    k_zero_out<<<gz, NT>>>(out);
    k_init<<<gBE, NT>>>(x);
    k_prep<<<dim3(Vn, G3 / 64), NT>>>(dec_Wih, dec_Wd2e, dec_bd2e, dec_bih, Mdec, cdec);
    k_prep<<<dim3(Vn, G3 / 64), NT>>>(enc_Wih, enc_Wd2e, enc_bd2e, enc_bih, Menc, cenc);

    dim3 gGates(Bn / 64, 4);
    dim3 gLog(Bn / 64);

    for (int t = 0; t < Tn; t++) {
        k_gates<<<gGates, NT>>>(hb[t & 1], hb[(t + 1) & 1], dec_Whh, dec_bhh, Mdec, cdec, tok);
        k_logits<<<gLog, NT>>>(hb[(t + 1) & 1], dec_We2d, dec_be2d, unif, out, t);
    }
    for (int t = 0; t < Tn; t++) {
        k_gates<<<gGates, NT>>>(heb[t & 1], heb[(t + 1) & 1], enc_Whh, enc_bhh, Menc, cenc, toks + t * Bn);
    }
    k_final<<<gBE, NT>>>(out);
}